// round 15
// baseline (speedup 1.0000x reference)
#include <cuda_runtime.h>
#include <math_constants.h>

#define N_NODES 100000
#define N_EDGES 1600000
#define D1 32
#define D2 16
#define FULL 0xffffffffu

// ---------------- scratch (device globals; no allocation allowed) -------------
__device__ __align__(16) float g_q   [N_NODES * D1];
__device__ __align__(16) float g_k   [N_NODES * D1];
__device__ __align__(16) float g_v   [N_NODES * D1];
__device__ __align__(16) float g_skip[N_NODES * D1];
__device__ __align__(16) float g_acc [N_NODES * D1];
__device__ __align__(16) float g_sk2 [N_NODES * D2];
__device__ float g_sum [N_NODES];

// ---------------- f32x2 packed-FMA helpers (B300 FFMA2 via PTX) ---------------
typedef unsigned long long u64;
__device__ __forceinline__ u64 pack2(float a, float b) {
    u64 r; asm("mov.b64 %0,{%1,%2};" : "=l"(r) : "f"(a), "f"(b)); return r;
}
__device__ __forceinline__ float2 unpk2(u64 p) {
    float2 r; asm("mov.b64 {%0,%1},%2;" : "=f"(r.x), "=f"(r.y) : "l"(p)); return r;
}
__device__ __forceinline__ u64 fma2(u64 a, u64 b, u64 c) {
    u64 r; asm("fma.rn.f32x2 %0,%1,%2,%3;" : "=l"(r) : "l"(a), "l"(b), "l"(c)); return r;
}
__device__ __forceinline__ u64 lds2(const float* p) {
    float2 v = *(const float2*)p;
    u64 r; asm("mov.b64 %0,{%1,%2};" : "=l"(r) : "f"(v.x), "f"(v.y)); return r;
}

__device__ __forceinline__ void redAdd4(float4* p, float a, float b, float c, float d) {
    asm volatile("red.global.add.v4.f32 [%0], {%1,%2,%3,%4};"
                 :: "l"(p), "f"(a), "f"(b), "f"(c), "f"(d) : "memory");
}

// ---------------- layer-1 projection (f32x2), fused acc/sum zeroing ----------
__global__ __launch_bounds__(256) void proj1_kernel(
        const float* __restrict__ x,
        const float* __restrict__ Wq, const float* __restrict__ bq,
        const float* __restrict__ Wk, const float* __restrict__ bk,
        const float* __restrict__ Wv, const float* __restrict__ bv,
        const float* __restrict__ Ws, const float* __restrict__ bs,
        int n) {
    constexpr int NPB = 16;
    __shared__ __align__(16) float sW[4][D1 * D1];
    __shared__ __align__(16) float sx[NPB][D1];
    int t = threadIdx.x;
    for (int i = t; i < D1 * D1; i += 256) {
        sW[0][i] = Wq[i]; sW[1][i] = Wk[i]; sW[2][i] = Wv[i]; sW[3][i] = Ws[i];
    }
    int node0 = blockIdx.x * NPB;
    for (int i = t; i < NPB * D1; i += 256) {
        int nn = node0 + (i >> 5);
        sx[i >> 5][i & 31] = (nn < n) ? x[(size_t)nn * D1 + (i & 31)] : 0.0f;
    }
    __syncthreads();
    int ln = t >> 4;                  // 0..15
    int j  = (t & 15) * 2;            // even dim pair
    int node = node0 + ln;
    if (node >= n) return;
    u64 aq = pack2(bq[j], bq[j+1]);
    u64 ak = pack2(bk[j], bk[j+1]);
    u64 av = pack2(bv[j], bv[j+1]);
    u64 as = pack2(bs[j], bs[j+1]);
    #pragma unroll
    for (int i = 0; i < D1; i++) {
        float xi = sx[ln][i];
        u64 x2 = pack2(xi, xi);
        aq = fma2(x2, lds2(&sW[0][i * D1 + j]), aq);
        ak = fma2(x2, lds2(&sW[1][i * D1 + j]), ak);
        av = fma2(x2, lds2(&sW[2][i * D1 + j]), av);
        as = fma2(x2, lds2(&sW[3][i * D1 + j]), as);
    }
    int o = node * D1 + j;
    *(float2*)(g_q + o)    = unpk2(aq);
    *(float2*)(g_k + o)    = unpk2(ak);
    *(float2*)(g_v + o)    = unpk2(av);
    *(float2*)(g_skip + o) = unpk2(as);
    *(float2*)(g_acc + o)  = make_float2(0.0f, 0.0f);
    if (j == 0) g_sum[node] = 0.0f;
}

// ---------------- fused edge pass: single-wave grid-stride, 4 lanes/edge -----
// 2368 blocks (148 SM x 8) all co-resident: zero wave transitions; consecutive
// edges per lane-group pipeline their gathers (high MLP). Math identical to R5.
#define EBLK 2368
template<int D>
__global__ __launch_bounds__(256, 8) void edge_fused_kernel(
        const int* __restrict__ src, const int* __restrict__ dst,
        float scale, int nE) {
    int gid = blockIdx.x * blockDim.x + threadIdx.x;
    int lane = gid & 3;
    int e0 = gid >> 2;
    const int estride = (EBLK * 256) >> 2;     // 151552 edge slots
    for (int e = e0; e < nE; e += estride) {
        int s = src[e], d = dst[e];
        const float4* qr = (const float4*)(g_q + (size_t)d * D);
        const float4* kr = (const float4*)(g_k + (size_t)s * D);
        float acc = 0.0f;
        #pragma unroll
        for (int i = 0; i < D / 16; i++) {
            float4 a = qr[i * 4 + lane];
            float4 b = kr[i * 4 + lane];
            acc = fmaf(a.x, b.x, fmaf(a.y, b.y, fmaf(a.z, b.z, fmaf(a.w, b.w, acc))));
        }
        unsigned m = __activemask();
        acc += __shfl_xor_sync(m, acc, 1, 4);
        acc += __shfl_xor_sync(m, acc, 2, 4);
        float w = __expf(fminf(acc * scale, 75.0f));   // overflow guard only
        if (lane == 0) atomicAdd(g_sum + d, w);
        const float4* vr = (const float4*)(g_v + (size_t)s * D);
        float4*       ar = (float4*)(g_acc + (size_t)d * D);
        #pragma unroll
        for (int i = 0; i < D / 16; i++) {
            float4 t = vr[i * 4 + lane];
            redAdd4(ar + i * 4 + lane, t.x * w, t.y * w, t.z * w, t.w * w);
        }
    }
}

// ---------------- fused: finalize layer 1 -> SMEM h -> layer-2 proj (f32x2) --
__global__ __launch_bounds__(256) void fin1_proj2_kernel(
        const float* __restrict__ Wq, const float* __restrict__ bq,
        const float* __restrict__ Wk, const float* __restrict__ bk,
        const float* __restrict__ Wv, const float* __restrict__ bv,
        const float* __restrict__ Ws, const float* __restrict__ bs,
        int n) {
    constexpr int NPB = 32;
    __shared__ __align__(16) float sW[4][D1 * D2];
    __shared__ __align__(16) float sh[NPB][D1];
    int t = threadIdx.x;
    for (int i = t; i < D1 * D2; i += 256) {
        sW[0][i] = Wq[i]; sW[1][i] = Wk[i]; sW[2][i] = Wv[i]; sW[3][i] = Ws[i];
    }
    int node0 = blockIdx.x * NPB;
    {   // Phase A: 32 nodes * 32 dims = 1024 floats = 256 float4, 1 per thread
        int ln = t >> 3;
        int c  = (t & 7) * 4;
        int node = node0 + ln;
        if (node < n) {
            int o = node * D1 + c;
            float4 a4 = *(const float4*)(g_acc + o);
            float4 s4 = *(const float4*)(g_skip + o);
            float inv = 1.0f / (g_sum[node] + 1e-16f);
            float4 h;
            h.x = fmaxf(fmaf(a4.x, inv, s4.x), 0.0f);
            h.y = fmaxf(fmaf(a4.y, inv, s4.y), 0.0f);
            h.z = fmaxf(fmaf(a4.z, inv, s4.z), 0.0f);
            h.w = fmaxf(fmaf(a4.w, inv, s4.w), 0.0f);
            *(float4*)&sh[ln][c] = h;
            *(float4*)(g_acc + o) = make_float4(0.0f, 0.0f, 0.0f, 0.0f);
            if (c == 0) g_sum[node] = 0.0f;
        }
    }
    __syncthreads();
    // Phase B: thread = (node ln, dim-pair jh); 4 FFMA2 per input dim.
    int ln = t >> 3;                  // 0..31
    int j  = (t & 7) * 2;             // even dim pair in 0..15
    int node = node0 + ln;
    if (node >= n) return;
    u64 aq = pack2(bq[j], bq[j+1]);
    u64 ak = pack2(bk[j], bk[j+1]);
    u64 av = pack2(bv[j], bv[j+1]);
    u64 as = pack2(bs[j], bs[j+1]);
    #pragma unroll
    for (int i = 0; i < D1; i++) {
        float hi = sh[ln][i];
        u64 h2 = pack2(hi, hi);
        aq = fma2(h2, lds2(&sW[0][i * D2 + j]), aq);
        ak = fma2(h2, lds2(&sW[1][i * D2 + j]), ak);
        av = fma2(h2, lds2(&sW[2][i * D2 + j]), av);
        as = fma2(h2, lds2(&sW[3][i * D2 + j]), as);
    }
    int o = node * D2 + j;
    *(float2*)(g_q + o)   = unpk2(aq);
    *(float2*)(g_k + o)   = unpk2(ak);
    *(float2*)(g_v + o)   = unpk2(av);
    *(float2*)(g_sk2 + o) = unpk2(as);
}

// ---------------- finalize layer 2 + output linear (16 -> 2), fused ----------
__global__ __launch_bounds__(256) void finalize2_out_kernel(
        const float* __restrict__ Wo, const float* __restrict__ bo,
        float* __restrict__ out, int n) {
    int tid = blockIdx.x * blockDim.x + threadIdx.x;
    if (tid >= n * D2) return;
    int node = tid >> 4;
    int i = tid & 15;
    float val = g_acc[tid] / (g_sum[node] + 1e-16f) + g_sk2[tid];
    val = fmaxf(val, 0.0f);
    float p0 = val * Wo[i * 2 + 0];
    float p1 = val * Wo[i * 2 + 1];
    unsigned m = __activemask();
    #pragma unroll
    for (int o = 8; o; o >>= 1) {
        p0 += __shfl_xor_sync(m, p0, o, 16);
        p1 += __shfl_xor_sync(m, p1, o, 16);
    }
    if (i == 0) {
        out[node * 2 + 0] = p0 + bo[0];
        out[node * 2 + 1] = p1 + bo[1];
    }
}

// ---------------- launch ------------------------------------------------------
extern "C" void kernel_launch(void* const* d_in, const int* in_sizes, int n_in,
                              void* d_out, int out_size) {
    const int*   ei  = (const int*)d_in[0];
    const float* emb = (const float*)d_in[1];
    const float *Wq1 = (const float*)d_in[2],  *bq1 = (const float*)d_in[3];
    const float *Wk1 = (const float*)d_in[4],  *bk1 = (const float*)d_in[5];
    const float *Wv1 = (const float*)d_in[6],  *bv1 = (const float*)d_in[7];
    const float *Ws1 = (const float*)d_in[8],  *bs1 = (const float*)d_in[9];
    const float *Wq2 = (const float*)d_in[10], *bq2 = (const float*)d_in[11];
    const float *Wk2 = (const float*)d_in[12], *bk2 = (const float*)d_in[13];
    const float *Wv2 = (const float*)d_in[14], *bv2 = (const float*)d_in[15];
    const float *Ws2 = (const float*)d_in[16], *bs2 = (const float*)d_in[17];
    const float *Wo  = (const float*)d_in[18], *bo  = (const float*)d_in[19];
    float* out = (float*)d_out;

    int E = in_sizes[0] / 2;
    int N = in_sizes[1] / D1;
    const int* src = ei;
    const int* dst = ei + E;

    const int TB = 256;
    int gP1 = (N + 15) / 16;                   // 16 nodes / block
    int gFP = (N + 31) / 32;                   // 32 nodes / block
    int gN2 = (N * D2 + TB - 1) / TB;

    float s1 = 1.0f / sqrtf((float)D1);
    float s2 = 1.0f / sqrtf((float)D2);

    // ---- layer 1 (d=32) ----
    proj1_kernel<<<gP1, TB>>>(emb, Wq1, bq1, Wk1, bk1, Wv1, bv1, Ws1, bs1, N);
    edge_fused_kernel<D1><<<EBLK, TB>>>(src, dst, s1, E);

    // ---- finalize 1 + projection 2 (fused) ----
    fin1_proj2_kernel<<<gFP, TB>>>(Wq2, bq2, Wk2, bk2, Wv2, bv2, Ws2, bs2, N);

    // ---- layer 2 (d=16) ----
    edge_fused_kernel<D2><<<EBLK, TB>>>(src, dst, s2, E);
    finalize2_out_kernel<<<gN2, TB>>>(Wo, bo, out, N);
}